// round 1
// baseline (speedup 1.0000x reference)
#include <cuda_runtime.h>

// _BaseFilter_51178830299244 : filtfilt (butter(4, 0.2)) over (8,64,48000) fp32.
//
// Strategy: overlap-recompute chunking. The IIR is stable (max |pole| ~= 0.796),
// so a chunk started W samples early from a zero state converges to the exact
// trajectory within 0.796^W (~3e-10 for W=96). Each thread owns one chunk of
// one row; forward pass writes the intermediate y1 to a static device scratch,
// backward pass reads it and writes the cropped output. Scaling by max|x| is
// skipped: the filter is linear, so it only changes rounding (~1e-7).

#define T_LEN   48000
#define PADL    15
#define TP      (T_LEN + 2 * PADL)     // 48030 padded length
#define ROWS    512                    // 8*64
#define L_CHUNK 376
#define N_CHUNK 128                    // 128*376 = 48128 >= 48030
#define WARM    96                     // warm-up: 0.796^96 ~ 3e-10

// Intermediate forward-filtered signal (padded coords), fp32.
__device__ float g_y1[(size_t)ROWS * TP];

// Filter coefficients (butter(4, 0.2), a0 == 1)
#define B0 0.004824343357716228f
#define B1 0.019297373430864913f
#define B2 0.02894606014629737f
#define B3 0.019297373430864913f
#define B4 0.004824343357716228f
#define A1 (-2.369513007182038f)
#define A2 ( 2.3139884144006455f)
#define A3 (-1.0546654058785672f)
#define A4 ( 0.18737949236818502f)

// Odd-padded signal value at padded coord t (reference _pad_odd semantics):
//   i = t-15;  i<0  -> 2*x[0]     - x[-1-i]
//              i>=T -> 2*x[T-1]   - x[2T-3-i]
__device__ __forceinline__ float load_xp_chk(const float* __restrict__ xr, int t) {
    int i = t - PADL;
    if (i < 0)      return 2.0f * xr[0]         - xr[-1 - i];
    if (i >= T_LEN) return 2.0f * xr[T_LEN - 1] - xr[2 * T_LEN - 3 - i];
    return xr[i];
}

template <bool CHK>
__device__ __forceinline__ void fwd_loop(const float* __restrict__ xr,
                                         float* __restrict__ y1r,
                                         int t0, int ps, int pe) {
    // x window: xw0 = xp[t-1], xw1 = xp[t-2], ...   IIR state s1 = y[t-1], ...
    float xw0 = 0.f, xw1 = 0.f, xw2 = 0.f, xw3 = 0.f;
    float s1 = 0.f, s2 = 0.f, s3 = 0.f, s4 = 0.f;
#pragma unroll 4
    for (int t = t0; t < pe; ++t) {
        float xn = CHK ? load_xp_chk(xr, t) : __ldg(xr + (t - PADL));
        float f = B0 * xn;
        f = fmaf(B1, xw0, f);
        f = fmaf(B2, xw1, f);
        f = fmaf(B3, xw2, f);
        f = fmaf(B4, xw3, f);
        // keep the y[t-1] dependency as the LAST fma (shortest critical chain)
        float acc = fmaf(-A2, s2, f);
        acc = fmaf(-A3, s3, acc);
        acc = fmaf(-A4, s4, acc);
        float y = fmaf(-A1, s1, acc);
        xw3 = xw2; xw2 = xw1; xw1 = xw0; xw0 = xn;
        s4 = s3; s3 = s2; s2 = s1; s1 = y;
        if (t >= ps) y1r[t] = y;
    }
}

__global__ void __launch_bounds__(N_CHUNK) fwd_kernel(const float* __restrict__ x) {
    int r = blockIdx.x;
    int c = threadIdx.x;
    const float* xr = x + (size_t)r * T_LEN;
    float* y1r = g_y1 + (size_t)r * TP;

    int ps = c * L_CHUNK;
    if (ps >= TP) return;
    int pe = min(ps + L_CHUNK, TP);
    int t0 = max(0, ps - WARM);        // t0 == 0 for chunk 0: exact zero-IC start

    bool chk = (t0 < PADL) || (pe > PADL + T_LEN);
    if (chk) fwd_loop<true>(xr, y1r, t0, ps, pe);
    else     fwd_loop<false>(xr, y1r, t0, ps, pe);
}

__global__ void __launch_bounds__(N_CHUNK) bwd_kernel(float* __restrict__ out) {
    int r = blockIdx.x;
    int c = threadIdx.x;
    const float* y1r = g_y1 + (size_t)r * TP;
    float* outr = out + (size_t)r * T_LEN;

    int ps = c * L_CHUNK;
    if (ps >= TP) return;
    int pe = min(ps + L_CHUNK, TP);
    int t1 = min(TP - 1, pe - 1 + WARM);  // t1 == TP-1 for last chunk: exact start
    int wlo = max(ps, PADL);              // crop: write only padded coords [15, 48015)
    int whi = min(pe, PADL + T_LEN);

    // window: w0 = y1[t+1], w1 = y1[t+2], ...  state s1 = y2[t+1], ...
    float w0 = 0.f, w1 = 0.f, w2 = 0.f, w3 = 0.f;
    float s1 = 0.f, s2 = 0.f, s3 = 0.f, s4 = 0.f;
#pragma unroll 4
    for (int t = t1; t >= ps; --t) {
        float yn = __ldg(y1r + t);
        float f = B0 * yn;
        f = fmaf(B1, w0, f);
        f = fmaf(B2, w1, f);
        f = fmaf(B3, w2, f);
        f = fmaf(B4, w3, f);
        float acc = fmaf(-A2, s2, f);
        acc = fmaf(-A3, s3, acc);
        acc = fmaf(-A4, s4, acc);
        float y = fmaf(-A1, s1, acc);
        w3 = w2; w2 = w1; w1 = w0; w0 = yn;
        s4 = s3; s3 = s2; s2 = s1; s1 = y;
        if (t >= wlo && t < whi) outr[t - PADL] = y;
    }
}

extern "C" void kernel_launch(void* const* d_in, const int* in_sizes, int n_in,
                              void* d_out, int out_size) {
    const float* x = (const float*)d_in[0];  // (8,64,48000) fp32
    // d_in[1] = b, d_in[2] = a : compile-time constants above
    float* out = (float*)d_out;              // (8,64,48000) fp32
    fwd_kernel<<<ROWS, N_CHUNK>>>(x);
    bwd_kernel<<<ROWS, N_CHUNK>>>(out);
}

// round 2
// speedup vs baseline: 1.6906x; 1.6906x over previous
#include <cuda_runtime.h>

// _BaseFilter_51178830299244 : filtfilt (butter(4,0.2)) over (8,64,48000) fp32.
//
// Fused single-kernel design: each block owns a half-row segment staged in
// shared memory. Forward and backward IIR passes run IN PLACE in smem using
// overlap-recompute chunking (96-sample warmup; max |pole| ~ 0.885, so
// 0.885^96 ~ 8e-6 local truncation, ~1e-6 global). Global loads/stores are
// fully coalesced; all serial-recursion traffic is conflict-free smem.

#define T_LEN  48000
#define PADL   15
#define TP     (T_LEN + 2 * PADL)   // 48030 padded length
#define ROWS   512
#define HALF   24015                // TP/2 : core samples per block
#define HALO   104                  // seam halo (>= warmup 96 + FIR taps)
#define EXT    (HALF + HALO)        // 24119 loaded samples per block
#define NTHR   256
#define L      95                   // chunk per thread; odd -> conflict-free smem
#define W      96                   // warmup length
#define BODY   (NTHR * L)           // 24320 >= EXT
#define SMEMN  (W + BODY + W)       // 24512 floats (zero aprons both ends)
#define SMEMB  (SMEMN * 4)          // 98048 bytes -> 2 blocks/SM

// butter(4, 0.2) coefficients (a0 == 1)
#define B0c 0.004824343357716228f
#define B1c 0.019297373430864913f
#define B2c 0.02894606014629737f
#define B3c 0.019297373430864913f
#define B4c 0.004824343357716228f
#define A1c (-2.369513007182038f)
#define A2c ( 2.3139884144006455f)
#define A3c (-1.0546654058785672f)
#define A4c ( 0.18737949236818502f)

// One IIR step. All multipliers are immediates -> FFMA-imm (rt_SMSP=1).
// The y[t-1] dependency is the LAST fma: 4-cycle critical chain per sample.
#define IIR_STEP(xn, yout)                                   \
    do {                                                     \
        float f_ = B0c * (xn);                               \
        f_ = fmaf(B1c, w0_, f_);                             \
        f_ = fmaf(B2c, w1_, f_);                             \
        f_ = fmaf(B3c, w2_, f_);                             \
        f_ = fmaf(B4c, w3_, f_);                             \
        f_ = fmaf(-A2c, s2_, f_);                            \
        f_ = fmaf(-A3c, s3_, f_);                            \
        f_ = fmaf(-A4c, s4_, f_);                            \
        (yout) = fmaf(-A1c, s1_, f_);                        \
        w3_ = w2_; w2_ = w1_; w1_ = w0_; w0_ = (xn);         \
        s4_ = s3_; s3_ = s2_; s2_ = s1_; s1_ = (yout);       \
    } while (0)

#define IIR_RESET() \
    float w0_ = 0.f, w1_ = 0.f, w2_ = 0.f, w3_ = 0.f, \
          s1_ = 0.f, s2_ = 0.f, s3_ = 0.f, s4_ = 0.f

__global__ void __launch_bounds__(NTHR, 2)
fused_filtfilt(const float* __restrict__ x, float* __restrict__ out) {
    extern __shared__ float smem_raw[];
    float* xsp = smem_raw + W;            // body coord 0 lives here
    const int tid = threadIdx.x;
    const int blk = blockIdx.x;
    const int r = blk >> 1;
    const int h = blk & 1;
    const float* __restrict__ xr = x + (size_t)r * T_LEN;
    float* __restrict__ outr = out + (size_t)r * T_LEN;
    const int e0 = h ? (HALF - HALO) : 0; // padded-coord of body[0]

    // ---- Load (coalesced) + zero aprons. Odd-pad reflection at row edges. ----
    for (int i = tid; i < SMEMN; i += NTHR) {
        int bi = i - W;                   // body index
        float v = 0.f;
        if (bi >= 0 && bi < EXT) {
            int j = e0 + bi - PADL;       // raw x index
            if (j < 0)           v = 2.f * xr[0]         - xr[-1 - j];
            else if (j >= T_LEN) v = 2.f * xr[T_LEN - 1] - xr[2 * T_LEN - 3 - j];
            else                 v = xr[j];
        }
        smem_raw[i] = v;
    }
    __syncthreads();

    const int ps = tid * L;               // this thread's chunk start (body coords)

    // ---- Forward pass (in place) ----
    {
        IIR_RESET();
        float y;
#pragma unroll 4
        for (int s = 0; s < W; ++s) {     // warmup: reads only
            float xn = xsp[ps - W + s];
            IIR_STEP(xn, y);
        }
        __syncthreads();                  // all cross-chunk reads done before writes
#pragma unroll 5
        for (int s = 0; s < L; ++s) {     // own chunk: read then overwrite in place
            int t = ps + s;
            float xn = xsp[t];
            IIR_STEP(xn, y);
            xsp[t] = y;
        }
    }
    __syncthreads();

    // ---- Backward pass (in place, reversed) ----
    {
        IIR_RESET();
        float y;
        const int tb = ps + L - 1 + W;    // warmup start (zero tail => exact at row end)
#pragma unroll 4
        for (int s = 0; s < W; ++s) {
            float yn = xsp[tb - s];
            IIR_STEP(yn, y);
        }
        __syncthreads();
#pragma unroll 5
        for (int s = 0; s < L; ++s) {
            int t = ps + L - 1 - s;
            float yn = xsp[t];
            IIR_STEP(yn, y);
            xsp[t] = y;
        }
    }
    __syncthreads();

    // ---- Store core ∩ [PADL, TP-PADL) (coalesced) ----
    const int core0 = h ? HALF : 0;
    const int core1 = h ? TP : HALF;
    const int wlo = core0 > PADL ? core0 : PADL;
    const int whi = core1 < (TP - PADL) ? core1 : (TP - PADL);
    for (int p = wlo + tid; p < whi; p += NTHR) {
        outr[p - PADL] = xsp[p - e0];
    }
}

extern "C" void kernel_launch(void* const* d_in, const int* in_sizes, int n_in,
                              void* d_out, int out_size) {
    const float* x = (const float*)d_in[0];   // (8,64,48000) fp32
    float* out = (float*)d_out;               // (8,64,48000) fp32
    cudaFuncSetAttribute(fused_filtfilt,
                         cudaFuncAttributeMaxDynamicSharedMemorySize, SMEMB);
    fused_filtfilt<<<ROWS * 2, NTHR, SMEMB>>>(x, out);
}

// round 3
// speedup vs baseline: 2.6963x; 1.5949x over previous
#include <cuda_runtime.h>

// filtfilt (butter(4,0.2)) over (8,64,48000) fp32 — fused smem kernel, v3.
// - 4 segments/row, 256 thr, ~50KB smem -> 4 blocks/SM (32 warps/SM).
// - Overlap-recompute chunking: W=80 warmup (max |pole| = 0.7955 -> 4e-7).
// - FIX vs v2: zero y1 beyond the loaded extent after the forward pass, so the
//   backward recursion at the row end sees exact zeros (reference zero-init),
//   not a spurious forward decay tail (that tail caused rel_err 8.9e-4).

#define T_LEN  48000
#define PADL   15
#define TP     (T_LEN + 2 * PADL)   // 48030
#define ROWS   512
#define NSEG   4
#define SEGC   12008                // core samples per segment (last: 12006)
#define NTHR   256
#define L      49                   // chunk/thread; odd -> conflict-free banks
#define W      80                   // warmup
#define HALO   88                   // seam halo (> W + taps)
#define BODY   (NTHR * L)           // 12544 >= SEGC + 2*HALO = 12184
#define SMEMN  (W + BODY + W)       // 12704 floats
#define SMEMB  (SMEMN * 4)          // 50816 B -> 4 blocks/SM

#define B0c 0.004824343357716228f
#define B1c 0.019297373430864913f
#define B2c 0.02894606014629737f
#define B3c 0.019297373430864913f
#define B4c 0.004824343357716228f
#define A1c (-2.369513007182038f)
#define A2c ( 2.3139884144006455f)
#define A3c (-1.0546654058785672f)
#define A4c ( 0.18737949236818502f)

#define IIR_STEP(xn, yout)                                   \
    do {                                                     \
        float f_ = B0c * (xn);                               \
        f_ = fmaf(B1c, w0_, f_);                             \
        f_ = fmaf(B2c, w1_, f_);                             \
        f_ = fmaf(B3c, w2_, f_);                             \
        f_ = fmaf(B4c, w3_, f_);                             \
        f_ = fmaf(-A2c, s2_, f_);                            \
        f_ = fmaf(-A3c, s3_, f_);                            \
        f_ = fmaf(-A4c, s4_, f_);                            \
        (yout) = fmaf(-A1c, s1_, f_);                        \
        w3_ = w2_; w2_ = w1_; w1_ = w0_; w0_ = (xn);         \
        s4_ = s3_; s3_ = s2_; s2_ = s1_; s1_ = (yout);       \
    } while (0)

#define IIR_RESET() \
    float w0_ = 0.f, w1_ = 0.f, w2_ = 0.f, w3_ = 0.f, \
          s1_ = 0.f, s2_ = 0.f, s3_ = 0.f, s4_ = 0.f

__global__ void __launch_bounds__(NTHR, 4)
fused_filtfilt(const float* __restrict__ x, float* __restrict__ out) {
    extern __shared__ float smem_raw[];
    float* xsp = smem_raw + W;              // body coord 0
    const int tid = threadIdx.x;
    const int blk = blockIdx.x;
    const int r = blk >> 2;
    const int sg = blk & 3;
    const float* __restrict__ xr = x + (size_t)r * T_LEN;
    float* __restrict__ outr = out + (size_t)r * T_LEN;

    const int core0 = sg * SEGC;
    const int core1 = min(core0 + SEGC, TP);
    const int e0 = max(0, core0 - HALO);    // padded coord of body[0]
    const int ext_end = min(TP, core1 + HALO);
    const int ext_len = ext_end - e0;       // valid body samples

    // ---- Load (coalesced) + zero aprons; odd-pad reflection at row edges ----
    for (int i = tid; i < SMEMN; i += NTHR) {
        int bi = i - W;
        float v = 0.f;
        if (bi >= 0 && bi < ext_len) {
            int j = e0 + bi - PADL;
            if (j < 0)           v = 2.f * xr[0]         - xr[-1 - j];
            else if (j >= T_LEN) v = 2.f * xr[T_LEN - 1] - xr[2 * T_LEN - 3 - j];
            else                 v = xr[j];
        }
        smem_raw[i] = v;
    }
    __syncthreads();

    const int ps = tid * L;

    // ---- Forward pass (in place) ----
    {
        IIR_RESET();
        float y;
#pragma unroll 4
        for (int s = 0; s < W; ++s) {
            float xn = xsp[ps - W + s];
            IIR_STEP(xn, y);
        }
        __syncthreads();                    // all cross-chunk reads before writes
#pragma unroll 7
        for (int s = 0; s < L; ++s) {
            int t = ps + s;
            float xn = xsp[t];
            IIR_STEP(xn, y);
            xsp[t] = y;
        }
    }
    __syncthreads();

    // ---- Re-zero y1 beyond the valid extent. For the last segment this makes
    //      the backward recursion start from exact zeros at the padded row end
    //      (reference semantics); elsewhere it is halo-protected either way. ----
    for (int i = ext_len + tid; i < BODY; i += NTHR) xsp[i] = 0.f;
    __syncthreads();

    // ---- Backward pass (in place, reversed) ----
    {
        IIR_RESET();
        float y;
        const int tb = ps + L - 1 + W;
#pragma unroll 4
        for (int s = 0; s < W; ++s) {
            float yn = xsp[tb - s];
            IIR_STEP(yn, y);
        }
        __syncthreads();
#pragma unroll 7
        for (int s = 0; s < L; ++s) {
            int t = ps + L - 1 - s;
            float yn = xsp[t];
            IIR_STEP(yn, y);
            xsp[t] = y;
        }
    }
    __syncthreads();

    // ---- Store core ∩ [PADL, TP-PADL) (coalesced) ----
    const int wlo = max(core0, PADL);
    const int whi = min(core1, TP - PADL);
    for (int p = wlo + tid; p < whi; p += NTHR) {
        outr[p - PADL] = xsp[p - e0];
    }
}

extern "C" void kernel_launch(void* const* d_in, const int* in_sizes, int n_in,
                              void* d_out, int out_size) {
    const float* x = (const float*)d_in[0];
    float* out = (float*)d_out;
    cudaFuncSetAttribute(fused_filtfilt,
                         cudaFuncAttributeMaxDynamicSharedMemorySize, SMEMB);
    fused_filtfilt<<<ROWS * NSEG, NTHR, SMEMB>>>(x, out);
}

// round 4
// speedup vs baseline: 4.3614x; 1.6176x over previous
#include <cuda_runtime.h>

// filtfilt (butter(4,0.2)) over (8,64,48000) fp32 — fused smem kernel, v4.
// vs v3: 6 segments/row (smem 34.2KB -> 6 blocks/SM, 48 warps = 75% occ cap),
// warmup W 80->48 (max |pole| = 0.7956 -> 0.7956^48 = 1.7e-5 << 1e-3),
// chunk L=33 (odd -> (33*lane)%32 = lane : conflict-free smem banks).

#define T_LEN  48000
#define PADL   15
#define TP     (T_LEN + 2 * PADL)   // 48030
#define ROWS   512
#define NSEG   6
#define SEGC   8005                 // NSEG*SEGC = 48030 exactly
#define NTHR   256
#define L      33                   // chunk per thread (odd)
#define W      48                   // warmup
#define HALO   52                   // seam halo (W + taps)
#define BODY   (NTHR * L)           // 8448 >= SEGC + 2*HALO = 8109
#define SMEMN  (W + BODY + W)       // 8544 floats
#define SMEMB  (SMEMN * 4)          // 34176 B -> 6 blocks/SM

#define B0c 0.004824343357716228f
#define B1c 0.019297373430864913f
#define B2c 0.02894606014629737f
#define B3c 0.019297373430864913f
#define B4c 0.004824343357716228f
#define A1c (-2.369513007182038f)
#define A2c ( 2.3139884144006455f)
#define A3c (-1.0546654058785672f)
#define A4c ( 0.18737949236818502f)

// One IIR step; constant multipliers -> FFMA-imm form. The loop-carried
// dependency through s1_ is the LAST fma (4-cycle recurrence).
#define IIR_STEP(xn, yout)                                   \
    do {                                                     \
        float f_ = B0c * (xn);                               \
        f_ = fmaf(B1c, w0_, f_);                             \
        f_ = fmaf(B2c, w1_, f_);                             \
        f_ = fmaf(B3c, w2_, f_);                             \
        f_ = fmaf(B4c, w3_, f_);                             \
        f_ = fmaf(-A2c, s2_, f_);                            \
        f_ = fmaf(-A3c, s3_, f_);                            \
        f_ = fmaf(-A4c, s4_, f_);                            \
        (yout) = fmaf(-A1c, s1_, f_);                        \
        w3_ = w2_; w2_ = w1_; w1_ = w0_; w0_ = (xn);         \
        s4_ = s3_; s3_ = s2_; s2_ = s1_; s1_ = (yout);       \
    } while (0)

#define IIR_RESET() \
    float w0_ = 0.f, w1_ = 0.f, w2_ = 0.f, w3_ = 0.f, \
          s1_ = 0.f, s2_ = 0.f, s3_ = 0.f, s4_ = 0.f

__global__ void __launch_bounds__(NTHR, 6)
fused_filtfilt(const float* __restrict__ x, float* __restrict__ out) {
    extern __shared__ float smem_raw[];
    float* xsp = smem_raw + W;               // body coord 0
    const int tid = threadIdx.x;
    const int blk = blockIdx.x;
    const int r = blk / NSEG;
    const int sg = blk - r * NSEG;
    const float* __restrict__ xr = x + (size_t)r * T_LEN;
    float* __restrict__ outr = out + (size_t)r * T_LEN;

    const int core0 = sg * SEGC;
    const int core1 = core0 + SEGC;          // NSEG*SEGC == TP exactly
    const int e0 = max(0, core0 - HALO);     // padded coord of body[0]
    const int ext_end = min(TP, core1 + HALO);
    const int ext_len = ext_end - e0;

    // ---- Load (coalesced) + zero aprons; odd-pad reflection at row edges ----
    if (sg == 0 || sg == NSEG - 1) {
        for (int i = tid; i < SMEMN; i += NTHR) {
            int bi = i - W;
            float v = 0.f;
            if (bi >= 0 && bi < ext_len) {
                int j = e0 + bi - PADL;
                if (j < 0)           v = 2.f * xr[0]         - xr[-1 - j];
                else if (j >= T_LEN) v = 2.f * xr[T_LEN - 1] - xr[2 * T_LEN - 3 - j];
                else                 v = xr[j];
            }
            smem_raw[i] = v;
        }
    } else {                                  // interior: no reflection possible
        const float* src = xr + (e0 - PADL);
        for (int i = tid; i < SMEMN; i += NTHR) {
            int bi = i - W;
            smem_raw[i] = (bi >= 0 && bi < ext_len) ? __ldg(src + bi) : 0.f;
        }
    }
    __syncthreads();

    const int ps = tid * L;

    // ---- Forward pass (in place) ----
    {
        IIR_RESET();
        float y;
#pragma unroll 4
        for (int s = 0; s < W; ++s) {
            float xn = xsp[ps - W + s];
            IIR_STEP(xn, y);
        }
        __syncthreads();                      // cross-chunk reads before writes
#pragma unroll 11
        for (int s = 0; s < L; ++s) {
            int t = ps + s;
            float xn = xsp[t];
            IIR_STEP(xn, y);
            xsp[t] = y;
        }
    }
    __syncthreads();

    // ---- Re-zero beyond valid extent: backward recursion at the padded row
    //      end must start from exact zeros (reference zero-init semantics). ----
    for (int i = ext_len + tid; i < BODY; i += NTHR) xsp[i] = 0.f;
    __syncthreads();

    // ---- Backward pass (in place, reversed) ----
    {
        IIR_RESET();
        float y;
        const int tb = ps + L - 1 + W;
#pragma unroll 4
        for (int s = 0; s < W; ++s) {
            float yn = xsp[tb - s];
            IIR_STEP(yn, y);
        }
        __syncthreads();
#pragma unroll 11
        for (int s = 0; s < L; ++s) {
            int t = ps + L - 1 - s;
            float yn = xsp[t];
            IIR_STEP(yn, y);
            xsp[t] = y;
        }
    }
    __syncthreads();

    // ---- Store core ∩ [PADL, TP-PADL) (coalesced) ----
    const int wlo = max(core0, PADL);
    const int whi = min(core1, TP - PADL);
    for (int p = wlo + tid; p < whi; p += NTHR) {
        outr[p - PADL] = xsp[p - e0];
    }
}

extern "C" void kernel_launch(void* const* d_in, const int* in_sizes, int n_in,
                              void* d_out, int out_size) {
    const float* x = (const float*)d_in[0];
    float* out = (float*)d_out;
    cudaFuncSetAttribute(fused_filtfilt,
                         cudaFuncAttributeMaxDynamicSharedMemorySize, SMEMB);
    fused_filtfilt<<<ROWS * NSEG, NTHR, SMEMB>>>(x, out);
}